// round 2
// baseline (speedup 1.0000x reference)
#include <cuda_runtime.h>
#include <cuda_bf16.h>
#include <math.h>

// Problem constants
#define NB   128          // batch
#define ND   20           // depth
#define NIN  64           // W*W
#define NHID 4096         // W^4
#define NE   4            // experts
#define SAMP_ELEMS (ND * NIN)       // 1280 per sample
#define OUT_MAIN   (NB * SAMP_ELEMS)

// ---------------- scratch (static device globals; no runtime alloc) ----------------
__device__ __align__(16) float g_flat[NB * NIN];
__device__ __align__(16) float g_h[NB * NHID];        // 2 MB
__device__ __align__(16) float g_logits[NB * NHID];   // 2 MB
__device__ int g_count[NE];
__device__ int g_list[NE * NB];

// packed f32x2 FMA (PTX ISA 8.6, sm_100+): d = a*b + d elementwise on a float pair
__device__ __forceinline__ void fma2(float2& d, const float2 a, const float2 b) {
#if defined(__CUDA_ARCH__) && (__CUDA_ARCH__ >= 1000)
    unsigned long long* dp = reinterpret_cast<unsigned long long*>(&d);
    asm volatile("fma.rn.f32x2 %0, %1, %2, %0;"
        : "+l"(*dp)
        : "l"(*reinterpret_cast<const unsigned long long*>(&a)),
          "l"(*reinterpret_cast<const unsigned long long*>(&b)));
#else
    d.x = fmaf(a.x, b.x, d.x);
    d.y = fmaf(a.y, b.y, d.y);
#endif
}

// ---------------- kernel 0: zero per-expert counters ----------------
__global__ void k_zero() {
    if (threadIdx.x < NE) g_count[threadIdx.x] = 0;
}

// ---------------- kernel 1: conv1+relu, conv2+relu, flatten, top-1 gate ----------------
// one block per sample, 256 threads
__global__ void k_conv_gate(const float* __restrict__ inp,
                            const float* __restrict__ c1w, const float* __restrict__ c1b,
                            const float* __restrict__ c2w, const float* __restrict__ c2b,
                            const float* __restrict__ wg) {
    const int b = blockIdx.x, tid = threadIdx.x;
    __shared__ float s_in[SAMP_ELEMS];   // (d, y, x)
    __shared__ float s_c1[5 * ND * NIN]; // 5 channels at a time: 6400 floats
    __shared__ float s_w1[270];
    __shared__ float s_w2[1800];
    __shared__ float s_flat[NIN];
    __shared__ float s_log[NE];

    for (int i = tid; i < SAMP_ELEMS; i += 256) s_in[i] = inp[b * SAMP_ELEMS + i];
    for (int i = tid; i < 270;  i += 256) s_w1[i] = c1w[i];
    for (int i = tid; i < 1800; i += 256) s_w2[i] = c2w[i];
    __syncthreads();

    const int out  = tid >> 2;   // 0..63 spatial output
    const int part = tid & 3;    // 4-way channel split
    const int oy = out >> 3, ox = out & 7;
    float acc2 = 0.0f;

    for (int half = 0; half < 2; half++) {
        const int cbase = half * 5;
        // conv1 (channels cbase..cbase+4), depth pad 1, spatial pad 1, relu
        for (int idx = tid; idx < 5 * ND * NIN; idx += 256) {
            const int c   = idx / (ND * NIN);
            const int rem = idx - c * (ND * NIN);
            const int d = rem >> 6;
            const int p = rem & 63;
            const int y = p >> 3, x = p & 7;
            float a = c1b[cbase + c];
            const float* wp = &s_w1[(cbase + c) * 27];
            #pragma unroll
            for (int kd = 0; kd < 3; kd++) {
                const int dd = d + kd - 1;
                if (dd < 0 || dd >= ND) continue;
                #pragma unroll
                for (int ky = 0; ky < 3; ky++) {
                    const int yy = y + ky - 1;
                    if (yy < 0 || yy >= 8) continue;
                    #pragma unroll
                    for (int kx = 0; kx < 3; kx++) {
                        const int xx = x + kx - 1;
                        if (xx < 0 || xx >= 8) continue;
                        a += wp[kd * 9 + ky * 3 + kx] * s_in[dd * 64 + yy * 8 + xx];
                    }
                }
            }
            s_c1[idx] = fmaxf(a, 0.0f);
        }
        __syncthreads();
        // conv2 partial accumulation (depth kernel = 20, no depth pad, spatial pad 1)
        for (int cl = 0; cl < 5; cl++) {
            const int c = cbase + cl;
            if ((c & 3) != part) continue;
            const float* wp = &s_w2[c * 180];
            const float* ip = &s_c1[cl * (ND * NIN)];
            for (int kd = 0; kd < ND; kd++) {
                #pragma unroll
                for (int ky = 0; ky < 3; ky++) {
                    const int yy = oy + ky - 1;
                    if (yy < 0 || yy >= 8) continue;
                    #pragma unroll
                    for (int kx = 0; kx < 3; kx++) {
                        const int xx = ox + kx - 1;
                        if (xx < 0 || xx >= 8) continue;
                        acc2 += wp[kd * 9 + ky * 3 + kx] * ip[kd * 64 + yy * 8 + xx];
                    }
                }
            }
        }
        __syncthreads();
    }
    // reduce the 4 channel-parts (adjacent lanes)
    acc2 += __shfl_xor_sync(0xffffffffu, acc2, 1);
    acc2 += __shfl_xor_sync(0xffffffffu, acc2, 2);
    if (part == 0) s_flat[out] = fmaxf(acc2 + c2b[0], 0.0f);
    __syncthreads();

    // gating: logits = flat @ w_gate (64x4); top-1 with gate value 1.0
    if (tid < NE) {
        float l = 0.0f;
        for (int q = 0; q < NIN; q++) l += s_flat[q] * wg[q * NE + tid];
        s_log[tid] = l;
    }
    __syncthreads();
    if (tid == 0) {
        int best = 0; float bv = s_log[0];
        #pragma unroll
        for (int e = 1; e < NE; e++) if (s_log[e] > bv) { bv = s_log[e]; best = e; }
        const int slot = atomicAdd(&g_count[best], 1);
        g_list[best * NB + slot] = b;
    }
    if (tid < NIN) g_flat[b * NIN + tid] = s_flat[tid];
}

// ---------------- kernel 2: aux loss from expert counts ----------------
__global__ void k_aux(float* __restrict__ out, int out_size) {
    if (out_size <= OUT_MAIN) return;
    float c0 = (float)g_count[0], c1 = (float)g_count[1];
    float c2 = (float)g_count[2], c3 = (float)g_count[3];
    const float m = (c0 + c1 + c2 + c3) * 0.25f;
    float var = (c0 - m) * (c0 - m) + (c1 - m) * (c1 - m)
              + (c2 - m) * (c2 - m) + (c3 - m) * (c3 - m);
    var *= (1.0f / 3.0f);                       // ddof=1
    const float cv = var / (m * m + 1e-10f);    // importance == load (top-1, gate=1)
    out[OUT_MAIN] = 2.0f * cv * 1e-2f;
}

// ---------------- kernel 3: h = relu(flat @ w1[e] + b1[e]), expert-grouped ----------------
// grid (32 n-tiles of 128, E, 4 m-chunks of 32), 256 threads
__global__ void k_h(const float* __restrict__ w1, const float* __restrict__ b1) {
    const int e = blockIdx.y, mc = blockIdx.z;
    const int cnt = g_count[e];
    const int m0 = mc * 32;
    if (m0 >= cnt) return;
    const int rows = min(32, cnt - m0);
    const int n0 = blockIdx.x * 128;
    const int tid = threadIdx.x;

    __shared__ __align__(16) float sA[32 * NIN];     // 8 KB
    __shared__ __align__(16) float sB[NIN * 128];    // 32 KB
    __shared__ int slist[32];

    if (tid < 32) slist[tid] = g_list[e * NB + m0 + min(tid, rows - 1)];
    __syncthreads();

    for (int i = tid; i < 32 * 16; i += 256) {       // A: 32 rows x 64 (float4)
        const int r = i >> 4, k4 = i & 15;
        ((float4*)sA)[r * 16 + k4] =
            *(const float4*)(g_flat + (size_t)slist[r] * NIN + k4 * 4);
    }
    for (int i = tid; i < NIN * 32; i += 256) {      // B: 64 x 128 (float4)
        const int r = i >> 5, c = i & 31;
        ((float4*)sB)[r * 32 + c] =
            *(const float4*)(w1 + ((size_t)e * NIN + r) * NHID + n0 + c * 4);
    }
    __syncthreads();

    const int tm = tid >> 5, tn = tid & 31;          // 8 x 32 thread grid, TM=4 TN=4
    float acc[4][4] = {};
    #pragma unroll 4
    for (int k = 0; k < NIN; k++) {
        float a[4], bv[4];
        #pragma unroll
        for (int i = 0; i < 4; i++) a[i] = sA[(tm * 4 + i) * NIN + k];
        #pragma unroll
        for (int j = 0; j < 4; j++) bv[j] = sB[k * 128 + tn + 32 * j];
        #pragma unroll
        for (int i = 0; i < 4; i++)
            #pragma unroll
            for (int j = 0; j < 4; j++) acc[i][j] += a[i] * bv[j];
    }
    #pragma unroll
    for (int i = 0; i < 4; i++) {
        const int r = tm * 4 + i;
        if (r >= rows) break;
        const int gb = slist[r];
        #pragma unroll
        for (int j = 0; j < 4; j++) {
            const int n = n0 + tn + 32 * j;
            g_h[(size_t)gb * NHID + n] = fmaxf(acc[i][j] + b1[e * NHID + n], 0.0f);
        }
    }
}

// ---------------- kernel 4: logits = h @ w2[e] + b2[e]  (the big GEMM) ----------------
// BM=32, BN=64, BK=16, 128 threads, double-buffered, packed-f32x2 FMAs.
// grid (64 n-tiles, E, 4 m-chunks)
__global__ void __launch_bounds__(128)
k_expert2(const float* __restrict__ w2, const float* __restrict__ b2) {
    const int e = blockIdx.y, mc = blockIdx.z;
    const int cnt = g_count[e];
    const int m0 = mc * 32;
    if (m0 >= cnt) return;
    const int rows = min(32, cnt - m0);
    const int n0 = blockIdx.x * 64;
    const int tid = threadIdx.x;
    const size_t wbase = (size_t)e * NHID * NHID;

    __shared__ __align__(16) float As[2][16 * 34];   // [k][m], pad 34 for banks
    __shared__ __align__(16) float Bs[2][16 * 64];
    __shared__ int slist[32];

    if (tid < 32) slist[tid] = g_list[e * NB + m0 + min(tid, rows - 1)];
    __syncthreads();

    const int arow = tid >> 2, aq = tid & 3;         // A load: row 0..31, 4 thr/row
    const size_t abase = (size_t)slist[arow] * NHID + aq * 4;

    float4 pa, pb0, pb1;
    const int NC = NHID / 16;

    // ---- preload chunk 0 ----
    {
        const int k0 = 0;
        pa  = *(const float4*)(g_h + abase + k0);
        {
            int idx = tid;            int r = idx >> 4, c = idx & 15;
            pb0 = *(const float4*)(w2 + wbase + (size_t)(k0 + r) * NHID + n0 + c * 4);
            idx = tid + 128;          r = idx >> 4; c = idx & 15;
            pb1 = *(const float4*)(w2 + wbase + (size_t)(k0 + r) * NHID + n0 + c * 4);
        }
        As[0][(aq * 4 + 0) * 34 + arow] = pa.x;
        As[0][(aq * 4 + 1) * 34 + arow] = pa.y;
        As[0][(aq * 4 + 2) * 34 + arow] = pa.z;
        As[0][(aq * 4 + 3) * 34 + arow] = pa.w;
        {
            int idx = tid;            int r = idx >> 4, c = idx & 15;
            *(float4*)(&Bs[0][r * 64 + c * 4]) = pb0;
            idx = tid + 128;          r = idx >> 4; c = idx & 15;
            *(float4*)(&Bs[0][r * 64 + c * 4]) = pb1;
        }
    }
    __syncthreads();

    const int tm = tid >> 4, tn = tid & 15;          // 8 x 16 grid: rows tm*4..+3, cols tn+16j
    float2 acc[2][4] = {};

    for (int c = 0; c < NC; ++c) {
        const int cur = c & 1;
        const bool more = (c + 1) < NC;
        if (more) {
            const int k0 = (c + 1) * 16;
            pa  = *(const float4*)(g_h + abase + k0);
            int idx = tid;            int r = idx >> 4, cc = idx & 15;
            pb0 = *(const float4*)(w2 + wbase + (size_t)(k0 + r) * NHID + n0 + cc * 4);
            idx = tid + 128;          r = idx >> 4; cc = idx & 15;
            pb1 = *(const float4*)(w2 + wbase + (size_t)(k0 + r) * NHID + n0 + cc * 4);
        }
        const float* Ab = &As[cur][0];
        const float* Bb = &Bs[cur][0];
        #pragma unroll
        for (int kk = 0; kk < 16; kk++) {
            const float2 a0 = *(const float2*)(Ab + kk * 34 + tm * 4);
            const float2 a1 = *(const float2*)(Ab + kk * 34 + tm * 4 + 2);
            #pragma unroll
            for (int j = 0; j < 4; j++) {
                const float bv = Bb[kk * 64 + tn + 16 * j];
                const float2 bb = make_float2(bv, bv);
                fma2(acc[0][j], a0, bb);
                fma2(acc[1][j], a1, bb);
            }
        }
        if (more) {
            const int nb = cur ^ 1;
            As[nb][(aq * 4 + 0) * 34 + arow] = pa.x;
            As[nb][(aq * 4 + 1) * 34 + arow] = pa.y;
            As[nb][(aq * 4 + 2) * 34 + arow] = pa.z;
            As[nb][(aq * 4 + 3) * 34 + arow] = pa.w;
            int idx = tid;            int r = idx >> 4, cc = idx & 15;
            *(float4*)(&Bs[nb][r * 64 + cc * 4]) = pb0;
            idx = tid + 128;          r = idx >> 4; cc = idx & 15;
            *(float4*)(&Bs[nb][r * 64 + cc * 4]) = pb1;
        }
        __syncthreads();
    }

    #pragma unroll
    for (int i2 = 0; i2 < 2; i2++) {
        const int r = tm * 4 + i2 * 2;
        #pragma unroll
        for (int j = 0; j < 4; j++) {
            const int col = n0 + tn + 16 * j;
            const float bias = b2[e * NHID + col];
            if (r < rows)
                g_logits[(size_t)slist[r] * NHID + col] = acc[i2][j].x + bias;
            if (r + 1 < rows)
                g_logits[(size_t)slist[r + 1] * NHID + col] = acc[i2][j].y + bias;
        }
    }
}

// ---------------- kernel 5: softmax(logits) -> per-sample transform -> sigmoid ----------------
// one block per sample, 256 threads
__global__ void k_out(const float* __restrict__ inp, float* __restrict__ out) {
    const int b = blockIdx.x, tid = threadIdx.x;
    __shared__ float sy[64 * 65];     // softmax values, padded pitch 65
    __shared__ float sx[SAMP_ELEMS];
    __shared__ float red[8];

    float lmax = -1e30f;
    for (int i = tid; i < NHID; i += 256) {
        const float v = g_logits[(size_t)b * NHID + i];
        sy[(i >> 6) * 65 + (i & 63)] = v;
        lmax = fmaxf(lmax, v);
    }
    #pragma unroll
    for (int o = 16; o; o >>= 1) lmax = fmaxf(lmax, __shfl_xor_sync(0xffffffffu, lmax, o));
    if ((tid & 31) == 0) red[tid >> 5] = lmax;
    __syncthreads();
    float bmax = red[0];
    #pragma unroll
    for (int w = 1; w < 8; w++) bmax = fmaxf(bmax, red[w]);
    __syncthreads();

    float s = 0.0f;
    for (int i = tid; i < NHID; i += 256) {
        const int idx = (i >> 6) * 65 + (i & 63);
        const float ev = __expf(sy[idx] - bmax);
        sy[idx] = ev;
        s += ev;
    }
    #pragma unroll
    for (int o = 16; o; o >>= 1) s += __shfl_xor_sync(0xffffffffu, s, o);
    if ((tid & 31) == 0) red[tid >> 5] = s;
    __syncthreads();
    float Z = 0.0f;
    #pragma unroll
    for (int w = 0; w < 8; w++) Z += red[w];
    const float invZ = 1.0f / Z;

    for (int i = tid; i < SAMP_ELEMS; i += 256) sx[i] = inp[b * SAMP_ELEMS + i];
    __syncthreads();

    for (int o = tid; o < SAMP_ELEMS; o += 256) {
        const int d = o >> 6, p = o & 63;
        const float* yr = &sy[p * 65];
        const float* xr = &sx[d * 64];
        float acc = 0.0f;
        #pragma unroll
        for (int q = 0; q < 64; q++) acc += yr[q] * xr[q];
        acc *= invZ;
        out[b * SAMP_ELEMS + o] = 1.0f / (1.0f + __expf(-acc));
    }
}

// ---------------- launch ----------------
extern "C" void kernel_launch(void* const* d_in, const int* in_sizes, int n_in,
                              void* d_out, int out_size) {
    const float* input = (const float*)d_in[0];
    const float* c1w   = (const float*)d_in[1];
    const float* c1b   = (const float*)d_in[2];
    const float* c2w   = (const float*)d_in[3];
    const float* c2b   = (const float*)d_in[4];
    const float* wg    = (const float*)d_in[5];
    const float* w1    = (const float*)d_in[6];
    const float* b1    = (const float*)d_in[7];
    const float* w2    = (const float*)d_in[8];
    const float* b2    = (const float*)d_in[9];
    float* out = (float*)d_out;

    k_zero<<<1, 32>>>();
    k_conv_gate<<<NB, 256>>>(input, c1w, c1b, c2w, c2b, wg);
    k_aux<<<1, 1>>>(out, out_size);
    k_h<<<dim3(32, NE, 4), 256>>>(w1, b1);
    k_expert2<<<dim3(64, NE, 4), 128>>>(w2, b2);
    k_out<<<NB, 256>>>(input, out);
}

// round 3
// speedup vs baseline: 1.3913x; 1.3913x over previous
#include <cuda_runtime.h>
#include <cuda_bf16.h>
#include <math.h>

// Problem constants
#define NB   128          // batch
#define ND   20           // depth
#define NIN  64           // W*W
#define NHID 4096         // W^4
#define NE   4            // experts
#define SAMP_ELEMS (ND * NIN)       // 1280 per sample
#define OUT_MAIN   (NB * SAMP_ELEMS)

#define KS    4                    // split-K factor for big GEMM
#define SLICE (NHID / KS)          // 1024
#define BK    16
#define NCH   (SLICE / BK)         // 64 chunks per slice

// ---------------- scratch (static device globals; zero-init at load) ----------------
__device__ __align__(16) float g_flat[NB * NIN];
__device__ __align__(16) float g_h[NB * NHID];            // 2 MB
__device__ __align__(16) float g_part[KS][NB * NHID];     // 8 MB split-K partials
__device__ int g_count[NE];
__device__ int g_list[NE * NB];
__device__ int g_expert[NB];

// packed f32x2 FMA (PTX ISA 8.6, sm_100+)
__device__ __forceinline__ void fma2(float2& d, const float2 a, const float2 b) {
#if defined(__CUDA_ARCH__) && (__CUDA_ARCH__ >= 1000)
    unsigned long long* dp = reinterpret_cast<unsigned long long*>(&d);
    asm volatile("fma.rn.f32x2 %0, %1, %2, %0;"
        : "+l"(*dp)
        : "l"(*reinterpret_cast<const unsigned long long*>(&a)),
          "l"(*reinterpret_cast<const unsigned long long*>(&b)));
#else
    d.x = fmaf(a.x, b.x, d.x);
    d.y = fmaf(a.y, b.y, d.y);
#endif
}

__device__ __forceinline__ unsigned smem_u32(const void* p) {
    return (unsigned)__cvta_generic_to_shared(p);
}
__device__ __forceinline__ void cp16(unsigned dst, const void* src) {
    asm volatile("cp.async.ca.shared.global [%0], [%1], 16;" :: "r"(dst), "l"(src));
}
__device__ __forceinline__ void cp_commit() {
    asm volatile("cp.async.commit_group;");
}
template<int N> __device__ __forceinline__ void cp_wait() {
    asm volatile("cp.async.wait_group %0;" :: "n"(N));
}

// ---------------- kernel 1: conv1+relu, conv2+relu, flatten, top-1 gate ----------------
// one block per sample, 256 threads
__global__ void k_conv_gate(const float* __restrict__ inp,
                            const float* __restrict__ c1w, const float* __restrict__ c1b,
                            const float* __restrict__ c2w, const float* __restrict__ c2b,
                            const float* __restrict__ wg) {
    const int b = blockIdx.x, tid = threadIdx.x;
    __shared__ float s_in[SAMP_ELEMS];   // (d, y, x)
    __shared__ float s_c1[5 * ND * NIN]; // 5 channels at a time
    __shared__ float s_w1[270];
    __shared__ float s_w2[1800];
    __shared__ float s_flat[NIN];
    __shared__ float s_log[NE];

    for (int i = tid; i < SAMP_ELEMS; i += 256) s_in[i] = inp[b * SAMP_ELEMS + i];
    for (int i = tid; i < 270;  i += 256) s_w1[i] = c1w[i];
    for (int i = tid; i < 1800; i += 256) s_w2[i] = c2w[i];
    __syncthreads();

    const int out  = tid >> 2;   // 0..63 spatial output
    const int part = tid & 3;    // 4-way channel split
    const int oy = out >> 3, ox = out & 7;
    float acc2 = 0.0f;

    for (int half = 0; half < 2; half++) {
        const int cbase = half * 5;
        for (int idx = tid; idx < 5 * ND * NIN; idx += 256) {
            const int c   = idx / (ND * NIN);
            const int rem = idx - c * (ND * NIN);
            const int d = rem >> 6;
            const int p = rem & 63;
            const int y = p >> 3, x = p & 7;
            float a = c1b[cbase + c];
            const float* wp = &s_w1[(cbase + c) * 27];
            #pragma unroll
            for (int kd = 0; kd < 3; kd++) {
                const int dd = d + kd - 1;
                if (dd < 0 || dd >= ND) continue;
                #pragma unroll
                for (int ky = 0; ky < 3; ky++) {
                    const int yy = y + ky - 1;
                    if (yy < 0 || yy >= 8) continue;
                    #pragma unroll
                    for (int kx = 0; kx < 3; kx++) {
                        const int xx = x + kx - 1;
                        if (xx < 0 || xx >= 8) continue;
                        a += wp[kd * 9 + ky * 3 + kx] * s_in[dd * 64 + yy * 8 + xx];
                    }
                }
            }
            s_c1[idx] = fmaxf(a, 0.0f);
        }
        __syncthreads();
        for (int cl = 0; cl < 5; cl++) {
            const int c = cbase + cl;
            if ((c & 3) != part) continue;
            const float* wp = &s_w2[c * 180];
            const float* ip = &s_c1[cl * (ND * NIN)];
            for (int kd = 0; kd < ND; kd++) {
                #pragma unroll
                for (int ky = 0; ky < 3; ky++) {
                    const int yy = oy + ky - 1;
                    if (yy < 0 || yy >= 8) continue;
                    #pragma unroll
                    for (int kx = 0; kx < 3; kx++) {
                        const int xx = ox + kx - 1;
                        if (xx < 0 || xx >= 8) continue;
                        acc2 += wp[kd * 9 + ky * 3 + kx] * ip[kd * 64 + yy * 8 + xx];
                    }
                }
            }
        }
        __syncthreads();
    }
    acc2 += __shfl_xor_sync(0xffffffffu, acc2, 1);
    acc2 += __shfl_xor_sync(0xffffffffu, acc2, 2);
    if (part == 0) s_flat[out] = fmaxf(acc2 + c2b[0], 0.0f);
    __syncthreads();

    if (tid < NE) {
        float l = 0.0f;
        for (int q = 0; q < NIN; q++) l += s_flat[q] * wg[q * NE + tid];
        s_log[tid] = l;
    }
    __syncthreads();
    if (tid == 0) {
        int best = 0; float bv = s_log[0];
        #pragma unroll
        for (int e = 1; e < NE; e++) if (s_log[e] > bv) { bv = s_log[e]; best = e; }
        const int slot = atomicAdd(&g_count[best], 1);
        g_list[best * NB + slot] = b;
        g_expert[b] = best;
    }
    if (tid < NIN) g_flat[b * NIN + tid] = s_flat[tid];
}

// ---------------- kernel 2: aux loss from expert counts ----------------
__global__ void k_aux(float* __restrict__ out, int out_size) {
    if (out_size <= OUT_MAIN) return;
    float c0 = (float)g_count[0], c1 = (float)g_count[1];
    float c2 = (float)g_count[2], c3 = (float)g_count[3];
    const float m = (c0 + c1 + c2 + c3) * 0.25f;
    float var = (c0 - m) * (c0 - m) + (c1 - m) * (c1 - m)
              + (c2 - m) * (c2 - m) + (c3 - m) * (c3 - m);
    var *= (1.0f / 3.0f);                       // ddof=1
    const float cv = var / (m * m + 1e-10f);
    out[OUT_MAIN] = 2.0f * cv * 1e-2f;
}

// ---------------- kernel 3: h = relu(flat @ w1[e] + b1[e]), expert-grouped ----------------
__global__ void k_h(const float* __restrict__ w1, const float* __restrict__ b1) {
    const int e = blockIdx.y, mc = blockIdx.z;
    const int cnt = g_count[e];
    const int m0 = mc * 32;
    if (m0 >= cnt) return;
    const int rows = min(32, cnt - m0);
    const int n0 = blockIdx.x * 128;
    const int tid = threadIdx.x;

    __shared__ __align__(16) float sA[32 * NIN];
    __shared__ __align__(16) float sB[NIN * 128];
    __shared__ int slist[32];

    if (tid < 32) slist[tid] = g_list[e * NB + m0 + min(tid, rows - 1)];
    __syncthreads();

    for (int i = tid; i < 32 * 16; i += 256) {
        const int r = i >> 4, k4 = i & 15;
        ((float4*)sA)[r * 16 + k4] =
            *(const float4*)(g_flat + (size_t)slist[r] * NIN + k4 * 4);
    }
    for (int i = tid; i < NIN * 32; i += 256) {
        const int r = i >> 5, c = i & 31;
        ((float4*)sB)[r * 32 + c] =
            *(const float4*)(w1 + ((size_t)e * NIN + r) * NHID + n0 + c * 4);
    }
    __syncthreads();

    const int tm = tid >> 5, tn = tid & 31;
    float acc[4][4] = {};
    #pragma unroll 4
    for (int k = 0; k < NIN; k++) {
        float a[4], bv[4];
        #pragma unroll
        for (int i = 0; i < 4; i++) a[i] = sA[(tm * 4 + i) * NIN + k];
        #pragma unroll
        for (int j = 0; j < 4; j++) bv[j] = sB[k * 128 + tn + 32 * j];
        #pragma unroll
        for (int i = 0; i < 4; i++)
            #pragma unroll
            for (int j = 0; j < 4; j++) acc[i][j] += a[i] * bv[j];
    }
    #pragma unroll
    for (int i = 0; i < 4; i++) {
        const int r = tm * 4 + i;
        if (r >= rows) break;
        const int gb = slist[r];
        #pragma unroll
        for (int j = 0; j < 4; j++) {
            const int n = n0 + tn + 32 * j;
            g_h[(size_t)gb * NHID + n] = fmaxf(acc[i][j] + b1[e * NHID + n], 0.0f);
        }
    }
}

// ---------------- kernel 4: split-K partials of logits = h @ w2[e] ----------------
// BM=32, BN=64, BK=16, 128 threads, 3-stage cp.async pipeline on B,
// register double-buffer on A. grid (64 n-tiles, NE*KS, 4 m-chunks).
__global__ void __launch_bounds__(128)
k_expert2(const float* __restrict__ w2) {
    const int e  = blockIdx.y >> 2;
    const int ks = blockIdx.y & 3;
    const int mc = blockIdx.z;
    const int cnt = g_count[e];
    const int m0 = mc * 32;
    if (m0 >= cnt) return;
    const int rows = min(32, cnt - m0);
    const int n0 = blockIdx.x * 64;
    const int tid = threadIdx.x;
    const size_t wbase = (size_t)e * NHID * NHID;
    const int kbase = ks * SLICE;

    __shared__ __align__(16) float Bs[3][BK * 64];   // 12 KB
    __shared__ __align__(16) float As[2][BK * 36];   // 4.5 KB, [k][m] pitch 36
    __shared__ int slist[32];

    if (tid < 32) slist[tid] = g_list[e * NB + m0 + min(tid, rows - 1)];
    __syncthreads();

    const int arow = tid >> 2, aq = tid & 3;
    const float* aptr = g_h + (size_t)slist[arow] * NHID + kbase + aq * 4;

    const int brow  = tid >> 4,          bseg  = tid & 15;
    const int brow2 = (tid + 128) >> 4,  bseg2 = (tid + 128) & 15;
    const float* bptr = w2 + wbase + (size_t)kbase * NHID + n0;

    // prologue: B chunk0 -> stage0, chunk1 -> stage1 (groups 0 and 1)
    cp16(smem_u32(&Bs[0][brow * 64 + bseg * 4]),   bptr + (size_t)brow  * NHID + bseg  * 4);
    cp16(smem_u32(&Bs[0][brow2 * 64 + bseg2 * 4]), bptr + (size_t)brow2 * NHID + bseg2 * 4);
    cp_commit();
    cp16(smem_u32(&Bs[1][brow * 64 + bseg * 4]),   bptr + (size_t)(BK + brow)  * NHID + bseg  * 4);
    cp16(smem_u32(&Bs[1][brow2 * 64 + bseg2 * 4]), bptr + (size_t)(BK + brow2) * NHID + bseg2 * 4);
    cp_commit();

    // A chunk0 -> As[0]
    {
        float4 pa0 = *(const float4*)(aptr);
        As[0][(aq * 4 + 0) * 36 + arow] = pa0.x;
        As[0][(aq * 4 + 1) * 36 + arow] = pa0.y;
        As[0][(aq * 4 + 2) * 36 + arow] = pa0.z;
        As[0][(aq * 4 + 3) * 36 + arow] = pa0.w;
    }

    const int tm = tid >> 4, tn = tid & 15;   // rows tm*4..+3, cols tn*4..+3
    float2 acc[4][2];
    #pragma unroll
    for (int i = 0; i < 4; i++) { acc[i][0] = make_float2(0.f, 0.f); acc[i][1] = make_float2(0.f, 0.f); }

    float4 pa = make_float4(0.f, 0.f, 0.f, 0.f);

    for (int c = 0; c < NCH; ++c) {
        if (c + 1 < NCH) pa = *(const float4*)(aptr + (size_t)(c + 1) * BK);
        if (c + 2 < NCH) {
            const int st = (c + 2) % 3;
            const size_t ko = (size_t)(c + 2) * BK;
            cp16(smem_u32(&Bs[st][brow * 64 + bseg * 4]),   bptr + (ko + brow)  * NHID + bseg  * 4);
            cp16(smem_u32(&Bs[st][brow2 * 64 + bseg2 * 4]), bptr + (ko + brow2) * NHID + bseg2 * 4);
        }
        cp_commit();           // one group per iteration (possibly empty)
        cp_wait<2>();          // chunk c's B resident
        __syncthreads();

        const float* Ab = &As[c & 1][0];
        const float* Bb = &Bs[c % 3][0];
        #pragma unroll
        for (int kk = 0; kk < BK; kk++) {
            const float4 av = *(const float4*)(Ab + kk * 36 + tm * 4);
            const float4 bv = *(const float4*)(Bb + kk * 64 + tn * 4);
            const float2 b0 = make_float2(bv.x, bv.y);
            const float2 b1 = make_float2(bv.z, bv.w);
            fma2(acc[0][0], make_float2(av.x, av.x), b0);
            fma2(acc[0][1], make_float2(av.x, av.x), b1);
            fma2(acc[1][0], make_float2(av.y, av.y), b0);
            fma2(acc[1][1], make_float2(av.y, av.y), b1);
            fma2(acc[2][0], make_float2(av.z, av.z), b0);
            fma2(acc[2][1], make_float2(av.z, av.z), b1);
            fma2(acc[3][0], make_float2(av.w, av.w), b0);
            fma2(acc[3][1], make_float2(av.w, av.w), b1);
        }

        if (c + 1 < NCH) {
            float* Ad = &As[(c & 1) ^ 1][0];
            Ad[(aq * 4 + 0) * 36 + arow] = pa.x;
            Ad[(aq * 4 + 1) * 36 + arow] = pa.y;
            Ad[(aq * 4 + 2) * 36 + arow] = pa.z;
            Ad[(aq * 4 + 3) * 36 + arow] = pa.w;
        }
        __syncthreads();
    }

    #pragma unroll
    for (int i = 0; i < 4; i++) {
        const int r = tm * 4 + i;
        if (r < rows) {
            float4 v = make_float4(acc[i][0].x, acc[i][0].y, acc[i][1].x, acc[i][1].y);
            *(float4*)(&g_part[ks][(size_t)slist[r] * NHID + n0 + tn * 4]) = v;
        }
    }
}

// ---------------- kernel 5: reduce partials + bias -> softmax -> transform -> sigmoid ----------------
// one block per sample, 256 threads
__global__ void k_out(const float* __restrict__ inp, const float* __restrict__ b2,
                      float* __restrict__ out) {
    const int b = blockIdx.x, tid = threadIdx.x;
    __shared__ float sy[64 * 65];     // softmax values, padded pitch 65
    __shared__ float sx[SAMP_ELEMS];
    __shared__ float red[8];

    // reset counters for next graph replay (k_out no longer needs them)
    if (b == 0 && tid < NE) g_count[tid] = 0;

    const int eb = g_expert[b];
    const float4* p0 = (const float4*)(&g_part[0][(size_t)b * NHID]);
    const float4* p1 = (const float4*)(&g_part[1][(size_t)b * NHID]);
    const float4* p2 = (const float4*)(&g_part[2][(size_t)b * NHID]);
    const float4* p3 = (const float4*)(&g_part[3][(size_t)b * NHID]);
    const float4* bb = (const float4*)(b2 + (size_t)eb * NHID);

    float lmax = -1e30f;
    for (int i4 = tid; i4 < NHID / 4; i4 += 256) {
        const float4 a = p0[i4], c = p1[i4], d = p2[i4], f = p3[i4], g = bb[i4];
        float4 s;
        s.x = a.x + c.x + d.x + f.x + g.x;
        s.y = a.y + c.y + d.y + f.y + g.y;
        s.z = a.z + c.z + d.z + f.z + g.z;
        s.w = a.w + c.w + d.w + f.w + g.w;
        const int i = i4 * 4;
        const int base = (i >> 6) * 65 + (i & 63);
        sy[base + 0] = s.x; sy[base + 1] = s.y; sy[base + 2] = s.z; sy[base + 3] = s.w;
        lmax = fmaxf(lmax, fmaxf(fmaxf(s.x, s.y), fmaxf(s.z, s.w)));
    }
    #pragma unroll
    for (int o = 16; o; o >>= 1) lmax = fmaxf(lmax, __shfl_xor_sync(0xffffffffu, lmax, o));
    if ((tid & 31) == 0) red[tid >> 5] = lmax;
    __syncthreads();
    float bmax = red[0];
    #pragma unroll
    for (int w = 1; w < 8; w++) bmax = fmaxf(bmax, red[w]);
    __syncthreads();

    float s = 0.0f;
    for (int i = tid; i < NHID; i += 256) {
        const int idx = (i >> 6) * 65 + (i & 63);
        const float ev = __expf(sy[idx] - bmax);
        sy[idx] = ev;
        s += ev;
    }
    #pragma unroll
    for (int o = 16; o; o >>= 1) s += __shfl_xor_sync(0xffffffffu, s, o);
    if ((tid & 31) == 0) red[tid >> 5] = s;
    __syncthreads();
    float Z = 0.0f;
    #pragma unroll
    for (int w = 0; w < 8; w++) Z += red[w];
    const float invZ = 1.0f / Z;

    for (int i = tid; i < SAMP_ELEMS; i += 256) sx[i] = inp[b * SAMP_ELEMS + i];
    __syncthreads();

    for (int o = tid; o < SAMP_ELEMS; o += 256) {
        const int d = o >> 6, p = o & 63;
        const float* yr = &sy[p * 65];
        const float* xr = &sx[d * 64];
        float acc = 0.0f;
        #pragma unroll
        for (int q = 0; q < 64; q++) acc += yr[q] * xr[q];
        acc *= invZ;
        out[b * SAMP_ELEMS + o] = 1.0f / (1.0f + __expf(-acc));
    }
}

// ---------------- launch ----------------
extern "C" void kernel_launch(void* const* d_in, const int* in_sizes, int n_in,
                              void* d_out, int out_size) {
    const float* input = (const float*)d_in[0];
    const float* c1w   = (const float*)d_in[1];
    const float* c1b   = (const float*)d_in[2];
    const float* c2w   = (const float*)d_in[3];
    const float* c2b   = (const float*)d_in[4];
    const float* wg    = (const float*)d_in[5];
    const float* w1    = (const float*)d_in[6];
    const float* b1    = (const float*)d_in[7];
    const float* w2    = (const float*)d_in[8];
    const float* b2    = (const float*)d_in[9];
    float* out = (float*)d_out;

    k_conv_gate<<<NB, 256>>>(input, c1w, c1b, c2w, c2b, wg);
    k_aux<<<1, 1>>>(out, out_size);
    k_h<<<dim3(32, NE, 4), 256>>>(w1, b1);
    k_expert2<<<dim3(64, NE * KS, 4), 128>>>(w2);
    k_out<<<NB, 256>>>(input, b2, out);
}

// round 5
// speedup vs baseline: 1.4114x; 1.0145x over previous
#include <cuda_runtime.h>
#include <cuda_bf16.h>
#include <math.h>

// Problem constants
#define NB   128          // batch
#define ND   20           // depth
#define NIN  64           // W*W
#define NHID 4096         // W^4
#define NE   4            // experts
#define SAMP_ELEMS (ND * NIN)       // 1280 per sample
#define OUT_MAIN   (NB * SAMP_ELEMS)

#define KS    4                    // split-K factor for big GEMM
#define SLICE (NHID / KS)          // 1024
#define BK    16
#define NCH   (SLICE / BK)         // 64 chunks per slice
#define BN2   128                  // k_expert2 N-tile

// ---------------- scratch (static device globals; zero-init at load) ----------------
__device__ __align__(16) float g_flat[NB * NIN];
__device__ __align__(16) float g_h[NB * NHID];            // 2 MB
__device__ __align__(16) float g_part[KS][NB * NHID];     // 8 MB split-K partials
__device__ int g_count[NE];
__device__ int g_list[NE * NB];
__device__ int g_expert[NB];

// packed f32x2 FMA (PTX ISA 8.6, sm_100+)
__device__ __forceinline__ void fma2(float2& d, const float2 a, const float2 b) {
#if defined(__CUDA_ARCH__) && (__CUDA_ARCH__ >= 1000)
    unsigned long long* dp = reinterpret_cast<unsigned long long*>(&d);
    asm volatile("fma.rn.f32x2 %0, %1, %2, %0;"
        : "+l"(*dp)
        : "l"(*reinterpret_cast<const unsigned long long*>(&a)),
          "l"(*reinterpret_cast<const unsigned long long*>(&b)));
#else
    d.x = fmaf(a.x, b.x, d.x);
    d.y = fmaf(a.y, b.y, d.y);
#endif
}

__device__ __forceinline__ unsigned smem_u32(const void* p) {
    return (unsigned)__cvta_generic_to_shared(p);
}
__device__ __forceinline__ void mbar_init(unsigned addr, unsigned count) {
    asm volatile("mbarrier.init.shared.b64 [%0], %1;" :: "r"(addr), "r"(count) : "memory");
}
__device__ __forceinline__ void mbar_expect_tx(unsigned addr, unsigned tx) {
    asm volatile("mbarrier.arrive.expect_tx.shared.b64 _, [%0], %1;"
                 :: "r"(addr), "r"(tx) : "memory");
}
__device__ __forceinline__ void bulk_g2s(unsigned dst, const void* src, unsigned bytes,
                                         unsigned mbar) {
    asm volatile(
        "cp.async.bulk.shared::cluster.global.mbarrier::complete_tx::bytes [%0], [%1], %2, [%3];"
        :: "r"(dst), "l"(src), "r"(bytes), "r"(mbar) : "memory");
}
__device__ __forceinline__ void mbar_wait(unsigned addr, unsigned parity) {
    unsigned done;
    asm volatile(
        "{\n\t.reg .pred p;\n\t"
        "mbarrier.try_wait.parity.acquire.cta.shared::cta.b64 p, [%1], %2;\n\t"
        "selp.b32 %0, 1, 0, p;\n\t}"
        : "=r"(done) : "r"(addr), "r"(parity) : "memory");
    if (!done) {
        asm volatile(
            "{\n\t.reg .pred P1;\n\t"
            "WL_%=:\n\t"
            "mbarrier.try_wait.parity.acquire.cta.shared::cta.b64 P1, [%0], %1, 0x989680;\n\t"
            "@P1 bra.uni WD_%=;\n\t"
            "bra.uni WL_%=;\n\t"
            "WD_%=:\n\t}"
            :: "r"(addr), "r"(parity) : "memory");
    }
}

// ---------------- kernel 1: conv1+relu, conv2+relu, flatten, top-1 gate ----------------
// one block per sample, 256 threads
__global__ void k_conv_gate(const float* __restrict__ inp,
                            const float* __restrict__ c1w, const float* __restrict__ c1b,
                            const float* __restrict__ c2w, const float* __restrict__ c2b,
                            const float* __restrict__ wg) {
    const int b = blockIdx.x, tid = threadIdx.x;
    __shared__ float s_in[SAMP_ELEMS];   // (d, y, x)
    __shared__ float s_c1[5 * ND * NIN]; // 5 channels at a time
    __shared__ float s_w1[270];
    __shared__ float s_w2[1800];
    __shared__ float s_flat[NIN];
    __shared__ float s_log[NE];

    for (int i = tid; i < SAMP_ELEMS; i += 256) s_in[i] = inp[b * SAMP_ELEMS + i];
    for (int i = tid; i < 270;  i += 256) s_w1[i] = c1w[i];
    for (int i = tid; i < 1800; i += 256) s_w2[i] = c2w[i];
    __syncthreads();

    const int out  = tid >> 2;   // 0..63 spatial output
    const int part = tid & 3;    // 4-way channel split
    const int oy = out >> 3, ox = out & 7;
    float acc2 = 0.0f;

    for (int half = 0; half < 2; half++) {
        const int cbase = half * 5;
        for (int idx = tid; idx < 5 * ND * NIN; idx += 256) {
            const int c   = idx / (ND * NIN);
            const int rem = idx - c * (ND * NIN);
            const int d = rem >> 6;
            const int p = rem & 63;
            const int y = p >> 3, x = p & 7;
            float a = c1b[cbase + c];
            const float* wp = &s_w1[(cbase + c) * 27];
            #pragma unroll
            for (int kd = 0; kd < 3; kd++) {
                const int dd = d + kd - 1;
                if (dd < 0 || dd >= ND) continue;
                #pragma unroll
                for (int ky = 0; ky < 3; ky++) {
                    const int yy = y + ky - 1;
                    if (yy < 0 || yy >= 8) continue;
                    #pragma unroll
                    for (int kx = 0; kx < 3; kx++) {
                        const int xx = x + kx - 1;
                        if (xx < 0 || xx >= 8) continue;
                        a += wp[kd * 9 + ky * 3 + kx] * s_in[dd * 64 + yy * 8 + xx];
                    }
                }
            }
            s_c1[idx] = fmaxf(a, 0.0f);
        }
        __syncthreads();
        for (int cl = 0; cl < 5; cl++) {
            const int c = cbase + cl;
            if ((c & 3) != part) continue;
            const float* wp = &s_w2[c * 180];
            const float* ip = &s_c1[cl * (ND * NIN)];
            for (int kd = 0; kd < ND; kd++) {
                #pragma unroll
                for (int ky = 0; ky < 3; ky++) {
                    const int yy = oy + ky - 1;
                    if (yy < 0 || yy >= 8) continue;
                    #pragma unroll
                    for (int kx = 0; kx < 3; kx++) {
                        const int xx = ox + kx - 1;
                        if (xx < 0 || xx >= 8) continue;
                        acc2 += wp[kd * 9 + ky * 3 + kx] * ip[kd * 64 + yy * 8 + xx];
                    }
                }
            }
        }
        __syncthreads();
    }
    acc2 += __shfl_xor_sync(0xffffffffu, acc2, 1);
    acc2 += __shfl_xor_sync(0xffffffffu, acc2, 2);
    if (part == 0) s_flat[out] = fmaxf(acc2 + c2b[0], 0.0f);
    __syncthreads();

    if (tid < NE) {
        float l = 0.0f;
        for (int q = 0; q < NIN; q++) l += s_flat[q] * wg[q * NE + tid];
        s_log[tid] = l;
    }
    __syncthreads();
    if (tid == 0) {
        int best = 0; float bv = s_log[0];
        #pragma unroll
        for (int e = 1; e < NE; e++) if (s_log[e] > bv) { bv = s_log[e]; best = e; }
        const int slot = atomicAdd(&g_count[best], 1);
        g_list[best * NB + slot] = b;
        g_expert[b] = best;
    }
    if (tid < NIN) g_flat[b * NIN + tid] = s_flat[tid];
}

// ---------------- kernel 2: aux loss from expert counts ----------------
__global__ void k_aux(float* __restrict__ out, int out_size) {
    if (out_size <= OUT_MAIN) return;
    float c0 = (float)g_count[0], c1 = (float)g_count[1];
    float c2 = (float)g_count[2], c3 = (float)g_count[3];
    const float m = (c0 + c1 + c2 + c3) * 0.25f;
    float var = (c0 - m) * (c0 - m) + (c1 - m) * (c1 - m)
              + (c2 - m) * (c2 - m) + (c3 - m) * (c3 - m);
    var *= (1.0f / 3.0f);                       // ddof=1
    const float cv = var / (m * m + 1e-10f);
    out[OUT_MAIN] = 2.0f * cv * 1e-2f;
}

// ---------------- kernel 3: h = relu(flat @ w1[e] + b1[e]), expert-grouped ----------------
__global__ void k_h(const float* __restrict__ w1, const float* __restrict__ b1) {
    const int e = blockIdx.y, mc = blockIdx.z;
    const int cnt = g_count[e];
    const int m0 = mc * 32;
    if (m0 >= cnt) return;
    const int rows = min(32, cnt - m0);
    const int n0 = blockIdx.x * 128;
    const int tid = threadIdx.x;

    __shared__ __align__(16) float sA[32 * NIN];
    __shared__ __align__(16) float sB[NIN * 128];
    __shared__ int slist[32];

    if (tid < 32) slist[tid] = g_list[e * NB + m0 + min(tid, rows - 1)];
    __syncthreads();

    for (int i = tid; i < 32 * 16; i += 256) {
        const int r = i >> 4, k4 = i & 15;
        ((float4*)sA)[r * 16 + k4] =
            *(const float4*)(g_flat + (size_t)slist[r] * NIN + k4 * 4);
    }
    for (int i = tid; i < NIN * 32; i += 256) {
        const int r = i >> 5, c = i & 31;
        ((float4*)sB)[r * 32 + c] =
            *(const float4*)(w1 + ((size_t)e * NIN + r) * NHID + n0 + c * 4);
    }
    __syncthreads();

    const int tm = tid >> 5, tn = tid & 31;
    float acc[4][4] = {};
    #pragma unroll 4
    for (int k = 0; k < NIN; k++) {
        float a[4], bv[4];
        #pragma unroll
        for (int i = 0; i < 4; i++) a[i] = sA[(tm * 4 + i) * NIN + k];
        #pragma unroll
        for (int j = 0; j < 4; j++) bv[j] = sB[k * 128 + tn + 32 * j];
        #pragma unroll
        for (int i = 0; i < 4; i++)
            #pragma unroll
            for (int j = 0; j < 4; j++) acc[i][j] += a[i] * bv[j];
    }
    #pragma unroll
    for (int i = 0; i < 4; i++) {
        const int r = tm * 4 + i;
        if (r >= rows) break;
        const int gb = slist[r];
        #pragma unroll
        for (int j = 0; j < 4; j++) {
            const int n = n0 + tn + 32 * j;
            g_h[(size_t)gb * NHID + n] = fmaxf(acc[i][j] + b1[e * NHID + n], 0.0f);
        }
    }
}

// ---------------- kernel 4: split-K partials of logits = h @ w2[e] ----------------
// BM=32, BN=128, BK=16, 256 threads. w2 stream via TMA bulk copies (3-stage,
// mbarrier complete_tx). A register-double-buffered through smem.
// grid (NHID/BN2=32 n-tiles, NE*KS=16, 4 m-chunks).
__global__ void __launch_bounds__(256)
k_expert2(const float* __restrict__ w2) {
    const int e  = blockIdx.y >> 2;
    const int ks = blockIdx.y & 3;
    const int mc = blockIdx.z;
    const int cnt = g_count[e];
    const int m0 = mc * 32;
    if (m0 >= cnt) return;
    const int rows = min(32, cnt - m0);
    const int n0 = blockIdx.x * BN2;
    const int tid = threadIdx.x;
    const size_t wbase = (size_t)e * NHID * NHID;
    const int kbase = ks * SLICE;

    __shared__ __align__(16) float Bs[3][BK * BN2];   // 24 KB
    __shared__ __align__(16) float As[2][BK * 36];    // 4.5 KB, [k][m] pitch 36
    __shared__ __align__(8)  unsigned long long s_mbar[3];
    __shared__ int slist[32];

    if (tid == 0) {
        #pragma unroll
        for (int s = 0; s < 3; s++) mbar_init(smem_u32(&s_mbar[s]), 1);
    }
    if (tid < 32) slist[tid] = g_list[e * NB + m0 + min(tid, rows - 1)];
    __syncthreads();

    const float* bptr = w2 + wbase + (size_t)kbase * NHID + n0;  // row-strided by NHID

    // B issue for chunk c into stage c%3 (threads 0..15, 1 row of 512B each)
    auto issue_b = [&](int c) {
        const int st = c % 3;
        const unsigned mb = smem_u32(&s_mbar[st]);
        if (tid == 0) mbar_expect_tx(mb, BK * BN2 * 4);
        if (tid < BK) {
            bulk_g2s(smem_u32(&Bs[st][tid * BN2]),
                     bptr + (size_t)(c * BK + tid) * NHID, BN2 * 4, mb);
        }
    };

    // A chunk load: threads 0..127, one float4 each (row=t>>2, k4=t&3)
    const int arow = tid >> 2, aq = tid & 3;
    const float* aptr = (tid < 128)
        ? g_h + (size_t)slist[arow] * NHID + kbase + aq * 4 : g_h;

    // prologue
    issue_b(0);
    issue_b(1);
    {
        float4 pa0 = make_float4(0.f, 0.f, 0.f, 0.f);
        if (tid < 128) pa0 = *(const float4*)(aptr);
        if (tid < 128) {
            As[0][(aq * 4 + 0) * 36 + arow] = pa0.x;
            As[0][(aq * 4 + 1) * 36 + arow] = pa0.y;
            As[0][(aq * 4 + 2) * 36 + arow] = pa0.z;
            As[0][(aq * 4 + 3) * 36 + arow] = pa0.w;
        }
    }
    __syncthreads();

    const int tm = tid >> 5, tn = tid & 31;   // rows tm*4..+3, cols tn*4..+3
    float2 acc[4][2];
    #pragma unroll
    for (int i = 0; i < 4; i++) { acc[i][0] = make_float2(0.f, 0.f); acc[i][1] = make_float2(0.f, 0.f); }

    float4 pa = make_float4(0.f, 0.f, 0.f, 0.f);

    for (int c = 0; c < NCH; ++c) {
        if (c + 2 < NCH) issue_b(c + 2);
        if (tid < 128 && c + 1 < NCH) pa = *(const float4*)(aptr + (size_t)(c + 1) * BK);

        mbar_wait(smem_u32(&s_mbar[c % 3]), (c / 3) & 1);

        const float* Ab = &As[c & 1][0];
        const float* Bb = &Bs[c % 3][0];
        #pragma unroll
        for (int kk = 0; kk < BK; kk++) {
            const float4 av = *(const float4*)(Ab + kk * 36 + tm * 4);
            const float4 bv = *(const float4*)(Bb + kk * BN2 + tn * 4);
            const float2 b0 = make_float2(bv.x, bv.y);
            const float2 b1 = make_float2(bv.z, bv.w);
            fma2(acc[0][0], make_float2(av.x, av.x), b0);
            fma2(acc[0][1], make_float2(av.x, av.x), b1);
            fma2(acc[1][0], make_float2(av.y, av.y), b0);
            fma2(acc[1][1], make_float2(av.y, av.y), b1);
            fma2(acc[2][0], make_float2(av.z, av.z), b0);
            fma2(acc[2][1], make_float2(av.z, av.z), b1);
            fma2(acc[3][0], make_float2(av.w, av.w), b0);
            fma2(acc[3][1], make_float2(av.w, av.w), b1);
        }

        if (tid < 128 && c + 1 < NCH) {
            float* Ad = &As[(c & 1) ^ 1][0];
            Ad[(aq * 4 + 0) * 36 + arow] = pa.x;
            Ad[(aq * 4 + 1) * 36 + arow] = pa.y;
            Ad[(aq * 4 + 2) * 36 + arow] = pa.z;
            Ad[(aq * 4 + 3) * 36 + arow] = pa.w;
        }
        __syncthreads();
    }

    #pragma unroll
    for (int i = 0; i < 4; i++) {
        const int r = tm * 4 + i;
        if (r < rows) {
            float4 v = make_float4(acc[i][0].x, acc[i][0].y, acc[i][1].x, acc[i][1].y);
            *(float4*)(&g_part[ks][(size_t)slist[r] * NHID + n0 + tn * 4]) = v;
        }
    }
}

// ---------------- kernel 5: reduce partials + bias -> softmax -> transform -> sigmoid ----------------
// one block per sample, 256 threads
__global__ void k_out(const float* __restrict__ inp, const float* __restrict__ b2,
                      float* __restrict__ out) {
    const int b = blockIdx.x, tid = threadIdx.x;
    __shared__ float sy[64 * 65];     // softmax values, padded pitch 65
    __shared__ float sx[SAMP_ELEMS];
    __shared__ float red[8];

    // reset counters for next graph replay
    if (b == 0 && tid < NE) g_count[tid] = 0;

    const int eb = g_expert[b];
    const float4* p0 = (const float4*)(&g_part[0][(size_t)b * NHID]);
    const float4* p1 = (const float4*)(&g_part[1][(size_t)b * NHID]);
    const float4* p2 = (const float4*)(&g_part[2][(size_t)b * NHID]);
    const float4* p3 = (const float4*)(&g_part[3][(size_t)b * NHID]);
    const float4* bb = (const float4*)(b2 + (size_t)eb * NHID);

    float lmax = -1e30f;
    for (int i4 = tid; i4 < NHID / 4; i4 += 256) {
        const float4 a = p0[i4], c = p1[i4], d = p2[i4], f = p3[i4], g = bb[i4];
        float4 s;
        s.x = a.x + c.x + d.x + f.x + g.x;
        s.y = a.y + c.y + d.y + f.y + g.y;
        s.z = a.z + c.z + d.z + f.z + g.z;
        s.w = a.w + c.w + d.w + f.w + g.w;
        const int i = i4 * 4;
        const int base = (i >> 6) * 65 + (i & 63);
        sy[base + 0] = s.x; sy[base + 1] = s.y; sy[base + 2] = s.z; sy[base + 3] = s.w;
        lmax = fmaxf(lmax, fmaxf(fmaxf(s.x, s.y), fmaxf(s.z, s.w)));
    }
    #pragma unroll
    for (int o = 16; o; o >>= 1) lmax = fmaxf(lmax, __shfl_xor_sync(0xffffffffu, lmax, o));
    if ((tid & 31) == 0) red[tid >> 5] = lmax;
    __syncthreads();
    float bmax = red[0];
    #pragma unroll
    for (int w = 1; w < 8; w++) bmax = fmaxf(bmax, red[w]);
    __syncthreads();

    float s = 0.0f;
    for (int i = tid; i < NHID; i += 256) {
        const int idx = (i >> 6) * 65 + (i & 63);
        const float ev = __expf(sy[idx] - bmax);
        sy[idx] = ev;
        s += ev;
    }
    #pragma unroll
    for (int o = 16; o; o >>= 1) s += __shfl_xor_sync(0xffffffffu, s, o);
    if ((tid & 31) == 0) red[tid >> 5] = s;
    __syncthreads();
    float Z = 0.0f;
    #pragma unroll
    for (int w = 0; w < 8; w++) Z += red[w];
    const float invZ = 1.0f / Z;

    for (int i = tid; i < SAMP_ELEMS; i += 256) sx[i] = inp[b * SAMP_ELEMS + i];
    __syncthreads();

    for (int o = tid; o < SAMP_ELEMS; o += 256) {
        const int d = o >> 6, p = o & 63;
        const float* yr = &sy[p * 65];
        const float* xr = &sx[d * 64];
        float acc = 0.0f;
        #pragma unroll
        for (int q = 0; q < 64; q++) acc += yr[q] * xr[q];
        acc *= invZ;
        out[b * SAMP_ELEMS + o] = 1.0f / (1.0f + __expf(-acc));
    }
}

// ---------------- launch ----------------
extern "C" void kernel_launch(void* const* d_in, const int* in_sizes, int n_in,
                              void* d_out, int out_size) {
    const float* input = (const float*)d_in[0];
    const float* c1w   = (const float*)d_in[1];
    const float* c1b   = (const float*)d_in[2];
    const float* c2w   = (const float*)d_in[3];
    const float* c2b   = (const float*)d_in[4];
    const float* wg    = (const float*)d_in[5];
    const float* w1    = (const float*)d_in[6];
    const float* b1    = (const float*)d_in[7];
    const float* w2    = (const float*)d_in[8];
    const float* b2    = (const float*)d_in[9];
    float* out = (float*)d_out;

    k_conv_gate<<<NB, 256>>>(input, c1w, c1b, c2w, c2b, wg);
    k_aux<<<1, 1>>>(out, out_size);
    k_h<<<dim3(32, NE, 4), 256>>>(w1, b1);
    k_expert2<<<dim3(NHID / BN2, NE * KS, 4), 256>>>(w2);
    k_out<<<NB, 256>>>(input, b2, out);
}